// round 2
// baseline (speedup 1.0000x reference)
#include <cuda_runtime.h>
#include <math.h>

#define B_ROWS 8192
#define C_COLS 32000

// Scratch (no device allocation allowed in kernel_launch)
__device__ float g_row_loss[B_ROWS];
__device__ int   g_y0_is64;   // 1 if y0 buffer holds int64 values, 0 if int32

// ---------------------------------------------------------------------------
// Detect y0 element width. Safe: only touches the first 512 bytes of y0,
// which exist for both int32 (32KB) and int64 (64KB) layouts.
// int64 little-endian => odd 32-bit words are high words == 0 (values < 2^31).
// int32 => odd words are random class indices in [0,32000); P(all zero) ~ 0.
__global__ void detect_y0_kernel(const int* __restrict__ y0w) {
    const int lane = threadIdx.x;           // 32 threads
    bool odd_zero = true;
    #pragma unroll
    for (int k = 0; k < 2; k++) {
        int w = y0w[2 * (lane + 32 * k) + 1];   // words 1,3,...,127
        if (w != 0) odd_zero = false;
    }
    unsigned all = __ballot_sync(0xFFFFFFFFu, odd_zero);
    if (lane == 0) g_y0_is64 = (all == 0xFFFFFFFFu) ? 1 : 0;
}

__device__ __forceinline__ void combine(float& m, float& s, float mo, float so) {
    float mn = fmaxf(m, mo);
    s = s * __expf(m - mn) + so * __expf(mo - mn);
    m = mn;
}

__global__ __launch_bounds__(256, 8)
void ce_row_kernel(const float* __restrict__ x,
                   const int* __restrict__ y0w,       // raw 32-bit view of y0
                   const float* __restrict__ a1_freq,
                   const int* __restrict__ gramma_ptr) {  // may be null
    const int row = blockIdx.x;
    const int tid = threadIdx.x;
    const float4* __restrict__ xr =
        reinterpret_cast<const float4*>(x + (size_t)row * C_COLS);

    // ---- single-pass online softmax over this row ----
    float m = -INFINITY;
    float s = 0.0f;

    const int nvec = C_COLS / 4;  // 8000 float4 per row
    for (int i = tid; i < nvec; i += 256) {
        float4 v = __ldg(&xr[i]);
        float vmax = fmaxf(fmaxf(v.x, v.y), fmaxf(v.z, v.w));
        if (vmax > m) {
            s *= __expf(m - vmax);
            m = vmax;
        }
        s += __expf(v.x - m);
        s += __expf(v.y - m);
        s += __expf(v.z - m);
        s += __expf(v.w - m);
    }

    // ---- warp reduce (m,s) ----
    #pragma unroll
    for (int o = 16; o > 0; o >>= 1) {
        float mo = __shfl_xor_sync(0xFFFFFFFFu, m, o);
        float so = __shfl_xor_sync(0xFFFFFFFFu, s, o);
        combine(m, s, mo, so);
    }

    // ---- block reduce across 8 warps ----
    __shared__ float sm_m[8];
    __shared__ float sm_s[8];
    const int warp = tid >> 5;
    const int lane = tid & 31;
    if (lane == 0) { sm_m[warp] = m; sm_s[warp] = s; }
    __syncthreads();

    if (warp == 0) {
        m = (lane < 8) ? sm_m[lane] : -INFINITY;
        s = (lane < 8) ? sm_s[lane] : 0.0f;
        #pragma unroll
        for (int o = 4; o > 0; o >>= 1) {
            float mo = __shfl_xor_sync(0xFFFFFFFFu, m, o);
            float so = __shfl_xor_sync(0xFFFFFFFFu, s, o);
            combine(m, s, mo, so);
        }
        if (lane == 0) {
            // 32-bit index read; position depends on detected element width.
            int t = g_y0_is64 ? __ldg(&y0w[2 * row]) : __ldg(&y0w[row]);
            float xt = __ldg(&x[(size_t)row * C_COLS + (size_t)t]);
            int g = gramma_ptr ? __ldg(gramma_ptr) : 1;  // low word == 1 for int32/int64
            float tw = 2.0f * __ldg(&a1_freq[row]);
            float w = (g == 1) ? tw : powf(tw, (float)g);
            g_row_loss[row] = w * (xt - m - __logf(s));
        }
    }
}

// Deterministic final reduction: fixed-order grid-stride + shuffle tree.
__global__ __launch_bounds__(1024, 1)
void ce_reduce_kernel(float* __restrict__ out) {
    const int tid = threadIdx.x;
    float acc = 0.0f;
    #pragma unroll
    for (int i = tid; i < B_ROWS; i += 1024) acc += g_row_loss[i];

    #pragma unroll
    for (int o = 16; o > 0; o >>= 1)
        acc += __shfl_xor_sync(0xFFFFFFFFu, acc, o);

    __shared__ float sm[32];
    const int warp = tid >> 5;
    const int lane = tid & 31;
    if (lane == 0) sm[warp] = acc;
    __syncthreads();
    if (warp == 0) {
        acc = sm[lane];
        #pragma unroll
        for (int o = 16; o > 0; o >>= 1)
            acc += __shfl_xor_sync(0xFFFFFFFFu, acc, o);
        if (lane == 0) out[0] = -acc / (float)B_ROWS;
    }
}

extern "C" void kernel_launch(void* const* d_in, const int* in_sizes, int n_in,
                              void* d_out, int out_size) {
    const float* x   = (const float*)d_in[0];
    const int*   y0w = (const int*)d_in[1];
    const float* af  = (const float*)d_in[2];
    const int*   gr  = (n_in > 3) ? (const int*)d_in[3] : (const int*)0;
    float* out = (float*)d_out;

    detect_y0_kernel<<<1, 32>>>(y0w);
    ce_row_kernel<<<B_ROWS, 256>>>(x, y0w, af, gr);
    ce_reduce_kernel<<<1, 1024>>>(out);
}